// round 14
// baseline (speedup 1.0000x reference)
#include <cuda_runtime.h>
#include <cuda_fp16.h>
#include <mma.h>
#include <cstdint>
using namespace nvcuda;

#define NB 8
#define NT 1024
#define NC 1024
#define NH 16
#define ND 64
#define NM (NB * NT)   // 8192

// K pre-scale: D^-0.5 * log2(e), folded into K so softmax is a bare exp2
#define KSCALE 0.1803368801111204f

// Scratch (device globals; fp16 activations)
__device__ __half g_q[NM * NC];
__device__ __half g_k[NM * NC];
__device__ __half g_v[NM * NC];
__device__ __half g_y[NM * NC];
__device__ __half g_xh[NM * NC];
__device__ __half g_wk[NC * NC];
__device__ __half g_wq[NC * NC];
__device__ __half g_wv[NC * NC];
__device__ __half g_wp[NC * NC];

// ---------------------------------------------------------------------------
// helpers
// ---------------------------------------------------------------------------
__device__ __forceinline__ uint32_t smem_u32(const void* p) {
    uint32_t a;
    asm("{ .reg .u64 t; cvta.to.shared.u64 t, %1; cvt.u32.u64 %0, t; }"
        : "=r"(a) : "l"(p));
    return a;
}
__device__ __forceinline__ void cp16(uint32_t dst, const void* src) {
    asm volatile("cp.async.cg.shared.global [%0], [%1], 16;"
                 :: "r"(dst), "l"(src));
}
#define CP_COMMIT() asm volatile("cp.async.commit_group;")
#define CP_WAIT(N)  asm volatile("cp.async.wait_group %0;" :: "n"(N))

__device__ __forceinline__ void ldm_x4(uint32_t* r, uint32_t addr) {
    asm volatile("ldmatrix.sync.aligned.m8n8.x4.shared.b16 {%0,%1,%2,%3}, [%4];"
                 : "=r"(r[0]), "=r"(r[1]), "=r"(r[2]), "=r"(r[3]) : "r"(addr));
}
__device__ __forceinline__ void ldm_x4t(uint32_t* r, uint32_t addr) {
    asm volatile("ldmatrix.sync.aligned.m8n8.x4.trans.shared.b16 {%0,%1,%2,%3}, [%4];"
                 : "=r"(r[0]), "=r"(r[1]), "=r"(r[2]), "=r"(r[3]) : "r"(addr));
}
__device__ __forceinline__ void mma16816(float* d, const uint32_t* a,
                                         uint32_t b0, uint32_t b1) {
    asm volatile(
        "mma.sync.aligned.m16n8k16.row.col.f32.f16.f16.f32 "
        "{%0,%1,%2,%3}, {%4,%5,%6,%7}, {%8,%9}, {%0,%1,%2,%3};"
        : "+f"(d[0]), "+f"(d[1]), "+f"(d[2]), "+f"(d[3])
        : "r"(a[0]), "r"(a[1]), "r"(a[2]), "r"(a[3]), "r"(b0), "r"(b1));
}
__device__ __forceinline__ float ex2(float x) {
    float r;
    asm("ex2.approx.f32 %0, %1;" : "=f"(r) : "f"(x));
    return r;
}

// ---------------------------------------------------------------------------
// fp32 -> fp16 converts
// ---------------------------------------------------------------------------
__global__ __launch_bounds__(256) void f2h_kernel(
    const float* __restrict__ in, __half* __restrict__ out, int n8)
{
    int i = blockIdx.x * blockDim.x + threadIdx.x;
    if (i >= n8) return;
    float4 v0 = ((const float4*)in)[2 * i];
    float4 v1 = ((const float4*)in)[2 * i + 1];
    __half2 h[4];
    h[0] = __floats2half2_rn(v0.x, v0.y);
    h[1] = __floats2half2_rn(v0.z, v0.w);
    h[2] = __floats2half2_rn(v1.x, v1.y);
    h[3] = __floats2half2_rn(v1.z, v1.w);
    ((uint4*)out)[i] = *(uint4*)h;
}

__global__ __launch_bounds__(256) void f2h4_kernel(
    const float* __restrict__ w0, const float* __restrict__ w1,
    const float* __restrict__ w2, const float* __restrict__ w3,
    __half* o0, __half* o1, __half* o2, __half* o3)
{
    const int z = blockIdx.z;
    const float* in = (z == 0) ? w0 : (z == 1) ? w1 : (z == 2) ? w2 : w3;
    __half* out = (z == 0) ? o0 : (z == 1) ? o1 : (z == 2) ? o2 : o3;
    int i = blockIdx.x * blockDim.x + threadIdx.x;
    float4 v0 = ((const float4*)in)[2 * i];
    float4 v1 = ((const float4*)in)[2 * i + 1];
    __half2 h[4];
    h[0] = __floats2half2_rn(v0.x, v0.y);
    h[1] = __floats2half2_rn(v0.z, v0.w);
    h[2] = __floats2half2_rn(v1.x, v1.y);
    h[3] = __floats2half2_rn(v1.z, v1.w);
    ((uint4*)out)[i] = *(uint4*)h;
}

// ---------------------------------------------------------------------------
// Persistent fp16 GEMM (R10 mainloop) + smem-staged COALESCED fp16 epilogue.
// ---------------------------------------------------------------------------
#define BM 128
#define BN 128
#define BK 64
#define GSTG 3
#define STG_A (BM * 128)
#define STG_B (BN * 128)
#define STG_BYTES (STG_A + STG_B)            // 32KB
#define EPI_LD 72                             // halves, padded row
#define EPI_WARP_BYTES (16 * EPI_LD * 2)      // 2304B per warp
#define EPI_BYTES (4 * EPI_WARP_BYTES)        // 9216B
#define GEMM_SMEM (GSTG * STG_BYTES + EPI_BYTES)   // 107520B
#define NKT (NC / BK)                         // 16

__global__ __launch_bounds__(128, 2) void hgemm_kernel(
    const __half* __restrict__ A,
    const __half* __restrict__ W0, const __half* __restrict__ W1,
    const __half* __restrict__ W2,
    __half* oh0, __half* oh1, __half* oh2,
    float* ofp, const float* __restrict__ bias,
    int ntot, float zsc)
{
    extern __shared__ char smem[];
    const uint32_t sb = smem_u32(smem);
    const int tid  = threadIdx.x;
    const int wid  = tid >> 5;
    const int lane = tid & 31;
    const int wm   = wid >> 1;
    const int wn   = wid & 1;

    int t_pf = blockIdx.x, kt_pf = 0;
    const char* pf_Ag = nullptr;
    const char* pf_Wg = nullptr;
    if (t_pf < ntot) {
        int z = t_pf >> 9, rm = t_pf & 511;
        const __half* W = (z == 0) ? W0 : (z == 1) ? W1 : W2;
        pf_Ag = (const char*)(A + (size_t)(rm >> 3) * (BM * NC));
        pf_Wg = (const char*)(W + (size_t)(rm & 7) * (BN * NC));
    }

    auto load_stage = [&](int s) {
        if (t_pf >= ntot) return;
        uint32_t base = sb + s * STG_BYTES;
#pragma unroll
        for (int i = 0; i < 8; i++) {
            int idx = i * 128 + tid;
            int row = idx >> 3, c = idx & 7;
            cp16(base + row * 128 + ((c ^ (row & 7)) << 4),
                 pf_Ag + (size_t)row * 2048 + kt_pf * 128 + c * 16);
        }
#pragma unroll
        for (int i = 0; i < 8; i++) {
            int idx = i * 128 + tid;
            int row = idx >> 3, c = idx & 7;
            cp16(base + STG_A + row * 128 + ((c ^ (row & 7)) << 4),
                 pf_Wg + (size_t)row * 2048 + kt_pf * 128 + c * 16);
        }
    };
    auto advance_pf = [&]() {
        if (++kt_pf == NKT) {
            kt_pf = 0;
            t_pf += gridDim.x;
            if (t_pf < ntot) {
                int z = t_pf >> 9, rm = t_pf & 511;
                const __half* W = (z == 0) ? W0 : (z == 1) ? W1 : W2;
                pf_Ag = (const char*)(A + (size_t)(rm >> 3) * (BM * NC));
                pf_Wg = (const char*)(W + (size_t)(rm & 7) * (BN * NC));
            }
        }
    };

    load_stage(0); CP_COMMIT(); advance_pf();
    load_stage(1); CP_COMMIT(); advance_pf();

    const int g  = lane >> 3;
    const int gi = lane & 7;
    int buf = 0;

    // per-warp epilogue staging pad
    __half* ep = (__half*)(smem + GSTG * STG_BYTES) + wid * 16 * EPI_LD;

    for (int t = blockIdx.x; t < ntot; t += gridDim.x) {
        float acc[4][8][4];
#pragma unroll
        for (int i = 0; i < 4; i++)
#pragma unroll
            for (int j = 0; j < 8; j++)
#pragma unroll
                for (int e = 0; e < 4; e++) acc[i][j][e] = 0.0f;

        for (int kt = 0; kt < NKT; kt++) {
            CP_WAIT(1);
            __syncthreads();
            load_stage((buf == 0) ? 2 : buf - 1);
            CP_COMMIT();
            advance_pf();

            uint32_t abase = sb + buf * STG_BYTES;
            uint32_t bbase = abase + STG_A;
#pragma unroll
            for (int ks = 0; ks < 4; ks++) {
                uint32_t afr[4][4];
#pragma unroll
                for (int mi = 0; mi < 4; mi++) {
                    int row = wm * 64 + mi * 16 + (g & 1) * 8 + gi;
                    int kc  = ks * 2 + (g >> 1);
                    ldm_x4(afr[mi], abase + row * 128 + ((kc ^ (row & 7)) << 4));
                }
                uint32_t bfr[4][4];
#pragma unroll
                for (int np = 0; np < 4; np++) {
                    int nrow = wn * 64 + np * 16 + (g >> 1) * 8 + gi;
                    int kc   = ks * 2 + (g & 1);
                    ldm_x4(bfr[np], bbase + nrow * 128 + ((kc ^ (nrow & 7)) << 4));
                }
#pragma unroll
                for (int mi = 0; mi < 4; mi++)
#pragma unroll
                    for (int np = 0; np < 4; np++)
#pragma unroll
                        for (int j = 0; j < 2; j++)
                            mma16816(acc[mi][np * 2 + j], afr[mi],
                                     bfr[np][2 * j], bfr[np][2 * j + 1]);
            }
            buf = (buf == 2) ? 0 : buf + 1;
        }

        const int z  = t >> 9, rm = t & 511;
        const int m0 = (rm >> 3) * BM;
        const int n0 = (rm & 7) * BN;
        const int r0c = lane >> 2;
        const int cc  = (lane & 3) * 2;

        if (ofp) {
            // fp32 + bias path: direct stores (float2, 32B/4-lane = OK)
#pragma unroll
            for (int mi = 0; mi < 4; mi++) {
#pragma unroll
                for (int ni = 0; ni < 8; ni++) {
                    int row = m0 + wm * 64 + mi * 16 + r0c;
                    int col = n0 + wn * 64 + ni * 8 + cc;
                    float* a = acc[mi][ni];
                    float2 b2 = *(const float2*)&bias[col];
                    *(float2*)&ofp[(size_t)row * NC + col] =
                        make_float2(a[0] + b2.x, a[1] + b2.y);
                    *(float2*)&ofp[(size_t)(row + 8) * NC + col] =
                        make_float2(a[2] + b2.x, a[3] + b2.y);
                }
            }
        } else {
            // fp16 path: stage 16-row slices in smem, re-read coalesced
            __half* oh = (z == 0) ? oh0 : (z == 1) ? oh1 : oh2;
            const float sc = (z == 0) ? zsc : 1.0f;
            const int rr  = lane >> 3;            // 0..3 (row within pass)
            const int ch  = (lane & 7) * 8;       // col chunk (halves)
#pragma unroll
            for (int mi = 0; mi < 4; mi++) {
#pragma unroll
                for (int ni = 0; ni < 8; ni++) {
                    float* a = acc[mi][ni];
                    __half2 h0 = __floats2half2_rn(a[0] * sc, a[1] * sc);
                    __half2 h1 = __floats2half2_rn(a[2] * sc, a[3] * sc);
                    *(__half2*)&ep[r0c * EPI_LD + ni * 8 + cc] = h0;
                    *(__half2*)&ep[(r0c + 8) * EPI_LD + ni * 8 + cc] = h1;
                }
                __syncwarp();
#pragma unroll
                for (int p = 0; p < 4; p++) {
                    int row = p * 4 + rr;
                    uint4 vdat = *(uint4*)&ep[row * EPI_LD + ch];
                    int grow = m0 + wm * 64 + mi * 16 + row;
                    *(uint4*)&oh[(size_t)grow * NC + n0 + wn * 64 + ch] = vdat;
                }
                __syncwarp();
            }
        }
    }
}

// ---------------------------------------------------------------------------
// Attention v8: BI=128 keys, 4 warps x 32 rows, 2 CTAs/SM, jt tile = 128
// queries, 2-buffer pipeline (prefetch distance 1 tile). jj-granular strips,
// K pre-scaled, p = ex2(s). Mask only in the diagonal tile.
// ---------------------------------------------------------------------------
#define BI 128
#define BJ 128
#define LDH 72
#define ATT_SMEM ((BI + 4 * BJ) * LDH * 2)   // 92160 bytes

__global__ __launch_bounds__(128, 2) void attn_kernel(
    const __half* __restrict__ q, const __half* __restrict__ k,
    const __half* __restrict__ v, __half* __restrict__ y)
{
    extern __shared__ char smraw[];
    __half* Ks = (__half*)smraw;            // 128 x 72 (reused for Y staging)
    __half* Qs = Ks + BI * LDH;             // 2 x 128 x 72
    __half* Vs = Qs + 2 * BJ * LDH;         // 2 x 128 x 72

    const int bh = blockIdx.x;
    const int b  = bh >> 4;
    const int h  = bh & 15;
    const int it = (int)(gridDim.y - 1) - (int)blockIdx.y;  // heavy first
    const int i0 = it * BI;
    const int jt_max = it;                  // tiles of 128 queries
    const int tid  = threadIdx.x;
    const int wid  = tid >> 5;
    const int lane = tid & 31;

    const __half* qg = q + (size_t)b * NT * NC + (size_t)h * ND;
    const __half* kg = k + (size_t)b * NT * NC + (size_t)h * ND;
    const __half* vg = v + (size_t)b * NT * NC + (size_t)h * ND;

    auto load_qv = [&](int jt) {
        int bufq = jt & 1;
        const __half* qsrc = qg + (size_t)(jt * BJ) * NC;
        const __half* vsrc = vg + (size_t)(jt * BJ) * NC;
        __half* qd = Qs + bufq * BJ * LDH;
        __half* vd = Vs + bufq * BJ * LDH;
#pragma unroll
        for (int i = 0; i < 8; i++) {
            int idx = i * 128 + tid;          // 1024 chunks each
            int r = idx >> 3, c = idx & 7;
            cp16(smem_u32(&qd[r * LDH + c * 8]), qsrc + (size_t)r * NC + c * 8);
            cp16(smem_u32(&vd[r * LDH + c * 8]), vsrc + (size_t)r * NC + c * 8);
        }
    };

    {   // prologue: K + QV(0) in one group
#pragma unroll
        for (int i = 0; i < 8; i++) {
            int idx = i * 128 + tid;
            int r = idx >> 3, c = idx & 7;
            cp16(smem_u32(&Ks[r * LDH + c * 8]),
                 kg + (size_t)(i0 + r) * NC + c * 8);
        }
        load_qv(0);
        CP_COMMIT();
    }

    const int ilocal = wid * 32;

    float yacc[2][8][4];
    float dsum[2][2];
    uint32_t ka[2][4][4];
#pragma unroll
    for (int mi = 0; mi < 2; mi++) {
        dsum[mi][0] = dsum[mi][1] = 0.0f;
#pragma unroll
        for (int f = 0; f < 8; f++)
#pragma unroll
            for (int e = 0; e < 4; e++) yacc[mi][f][e] = 0.0f;
    }

    auto body = [&](int jt, bool need_mask) {
        CP_WAIT(0);              // QV(jt) complete (issued 1 tile ago)
        __syncthreads();         // visibility + old buffer free
        if (jt + 1 <= jt_max) load_qv(jt + 1);
        CP_COMMIT();

        const __half* qbuf = Qs + (jt & 1) * BJ * LDH;
        const __half* vbuf = Vs + (jt & 1) * BJ * LDH;

        if (jt == 0) {   // hoist K A-fragments
#pragma unroll
            for (int mi = 0; mi < 2; mi++)
#pragma unroll
                for (int d = 0; d < 4; d++)
                    ldm_x4(ka[mi][d],
                           smem_u32(&Ks[(ilocal + mi * 16 + (lane & 15)) * LDH +
                                        d * 16 + ((lane >> 4) << 3)]));
        }

#pragma unroll
        for (int jj = 0; jj < 8; jj++) {
            float sacc[2][2][4];
#pragma unroll
            for (int mi = 0; mi < 2; mi++)
#pragma unroll
                for (int j = 0; j < 2; j++)
#pragma unroll
                    for (int e = 0; e < 4; e++) sacc[mi][j][e] = 0.0f;

#pragma unroll
            for (int d = 0; d < 4; d++) {
                uint32_t qf[4];
                ldm_x4(qf, smem_u32(&qbuf[(jj * 16 + ((lane >> 4) << 3) +
                                           (lane & 7)) * LDH +
                                          d * 16 + (((lane >> 3) & 1) << 3)]));
#pragma unroll
                for (int mi = 0; mi < 2; mi++) {
                    mma16816(sacc[mi][0], ka[mi][d], qf[0], qf[1]);
                    mma16816(sacc[mi][1], ka[mi][d], qf[2], qf[3]);
                }
            }

            uint32_t pa[2][2][2];
#pragma unroll
            for (int mi = 0; mi < 2; mi++) {
                const int ig0 = i0 + ilocal + mi * 16 + (lane >> 2);
#pragma unroll
                for (int j = 0; j < 2; j++) {
                    const int nt = jj * 2 + j;
                    float p0 = ex2(sacc[mi][j][0]);
                    float p1 = ex2(sacc[mi][j][1]);
                    float p2 = ex2(sacc[mi][j][2]);
                    float p3 = ex2(sacc[mi][j][3]);
                    if (need_mask) {
                        int jg = jt * BJ + nt * 8 + ((lane & 3) << 1);
                        if (jg     > ig0)     p0 = 0.0f;
                        if (jg + 1 > ig0)     p1 = 0.0f;
                        if (jg     > ig0 + 8) p2 = 0.0f;
                        if (jg + 1 > ig0 + 8) p3 = 0.0f;
                    }
                    dsum[mi][0] += p0 + p1;
                    dsum[mi][1] += p2 + p3;
                    __half2 h01 = __floats2half2_rn(p0, p1);
                    __half2 h23 = __floats2half2_rn(p2, p3);
                    pa[mi][j][0] = *(uint32_t*)&h01;
                    pa[mi][j][1] = *(uint32_t*)&h23;
                }
            }

            uint32_t vf[4][4];
#pragma unroll
            for (int dd = 0; dd < 4; dd++)
                ldm_x4t(vf[dd],
                        smem_u32(&vbuf[(jj * 16 + (lane & 15)) * LDH +
                                       dd * 16 + ((lane >> 4) << 3)]));
#pragma unroll
            for (int mi = 0; mi < 2; mi++) {
                uint32_t af[4] = { pa[mi][0][0], pa[mi][0][1],
                                   pa[mi][1][0], pa[mi][1][1] };
#pragma unroll
                for (int dd = 0; dd < 4; dd++) {
                    mma16816(yacc[mi][dd * 2],     af, vf[dd][0], vf[dd][1]);
                    mma16816(yacc[mi][dd * 2 + 1], af, vf[dd][2], vf[dd][3]);
                }
            }
        }
    };

    int jt = 0;
    for (; jt < jt_max; jt++) body(jt, false);
    body(jt_max, true);

    float inv[2][2];
#pragma unroll
    for (int mi = 0; mi < 2; mi++) {
#pragma unroll
        for (int e = 0; e < 2; e++) {
            float s = dsum[mi][e];
            s += __shfl_xor_sync(0xFFFFFFFFu, s, 1);
            s += __shfl_xor_sync(0xFFFFFFFFu, s, 2);
            inv[mi][e] = 1.0f / s;
        }
    }

    {
        int r = lane >> 2, cb = (lane & 3) << 1;
#pragma unroll
        for (int mi = 0; mi < 2; mi++)
#pragma unroll
            for (int nt = 0; nt < 8; nt++) {
                __half2 h0 = __floats2half2_rn(yacc[mi][nt][0] * inv[mi][0],
                                               yacc[mi][nt][1] * inv[mi][0]);
                __half2 h1 = __floats2half2_rn(yacc[mi][nt][2] * inv[mi][1],
                                               yacc[mi][nt][3] * inv[mi][1]);
                *(__half2*)&Ks[(ilocal + mi * 16 + r) * LDH + nt * 8 + cb] = h0;
                *(__half2*)&Ks[(ilocal + mi * 16 + r + 8) * LDH + nt * 8 + cb] = h1;
            }
    }
    __syncthreads();
    {
        __half* yg = y + (size_t)b * NT * NC + (size_t)h * ND;
#pragma unroll
        for (int i = 0; i < 8; i++) {
            int idx = i * 128 + tid;
            int r = idx >> 3, c = idx & 7;
            *(uint4*)&yg[(size_t)(i0 + r) * NC + c * 8] =
                *(uint4*)&Ks[r * LDH + c * 8];
        }
    }
}

// ---------------------------------------------------------------------------
extern "C" void kernel_launch(void* const* d_in, const int* in_sizes, int n_in,
                              void* d_out, int out_size)
{
    const float* x  = (const float*)d_in[0];
    const float* Wk = (const float*)d_in[1];
    const float* Wq = (const float*)d_in[2];
    const float* Wv = (const float*)d_in[3];
    const float* Wp = (const float*)d_in[4];
    const float* bp = (const float*)d_in[5];
    float* out = (float*)d_out;

    __half *qb, *kb, *vb, *yb, *xh, *wk, *wq, *wv, *wp;
    cudaGetSymbolAddress((void**)&qb, g_q);
    cudaGetSymbolAddress((void**)&kb, g_k);
    cudaGetSymbolAddress((void**)&vb, g_v);
    cudaGetSymbolAddress((void**)&yb, g_y);
    cudaGetSymbolAddress((void**)&xh, g_xh);
    cudaGetSymbolAddress((void**)&wk, g_wk);
    cudaGetSymbolAddress((void**)&wq, g_wq);
    cudaGetSymbolAddress((void**)&wv, g_wv);
    cudaGetSymbolAddress((void**)&wp, g_wp);

    int nsm = 148;
    cudaDeviceGetAttribute(&nsm, cudaDevAttrMultiProcessorCount, 0);
    const int pgrid = 2 * nsm;

    f2h_kernel<<<(NM * NC / 8 + 255) / 256, 256>>>(x, xh, NM * NC / 8);
    f2h4_kernel<<<dim3(NC * NC / 8 / 256, 1, 4), 256>>>(
        Wk, Wq, Wv, Wp, wk, wq, wv, wp);

    cudaFuncSetAttribute(hgemm_kernel,
                         cudaFuncAttributeMaxDynamicSharedMemorySize, GEMM_SMEM);

    hgemm_kernel<<<pgrid, 128, GEMM_SMEM>>>(
        xh, wk, wq, wv, kb, qb, vb, nullptr, nullptr, 1536, KSCALE);

    cudaFuncSetAttribute(attn_kernel,
                         cudaFuncAttributeMaxDynamicSharedMemorySize, ATT_SMEM);
    attn_kernel<<<dim3(NB * NH, NT / BI), 128, ATT_SMEM>>>(qb, kb, vb, yb);

    hgemm_kernel<<<pgrid, 128, GEMM_SMEM>>>(
        yb, wp, wp, wp, nullptr, nullptr, nullptr, out, bp, 512, 1.0f);
}

// round 15
// speedup vs baseline: 1.0242x; 1.0242x over previous
#include <cuda_runtime.h>
#include <cuda_fp16.h>
#include <mma.h>
#include <cstdint>
using namespace nvcuda;

#define NB 8
#define NT 1024
#define NC 1024
#define NH 16
#define ND 64
#define NM (NB * NT)   // 8192

// K pre-scale: D^-0.5 * log2(e), folded into K so softmax is a bare exp2
#define KSCALE 0.1803368801111204f

// Scratch (device globals; fp16 activations)
__device__ __half g_q[NM * NC];
__device__ __half g_k[NM * NC];
__device__ __half g_v[NM * NC];
__device__ __half g_y[NM * NC];
__device__ __half g_xh[NM * NC];
__device__ __half g_wk[NC * NC];
__device__ __half g_wq[NC * NC];
__device__ __half g_wv[NC * NC];
__device__ __half g_wp[NC * NC];

// ---------------------------------------------------------------------------
// helpers
// ---------------------------------------------------------------------------
__device__ __forceinline__ uint32_t smem_u32(const void* p) {
    uint32_t a;
    asm("{ .reg .u64 t; cvta.to.shared.u64 t, %1; cvt.u32.u64 %0, t; }"
        : "=r"(a) : "l"(p));
    return a;
}
__device__ __forceinline__ void cp16(uint32_t dst, const void* src) {
    asm volatile("cp.async.cg.shared.global [%0], [%1], 16;"
                 :: "r"(dst), "l"(src));
}
#define CP_COMMIT() asm volatile("cp.async.commit_group;")
#define CP_WAIT(N)  asm volatile("cp.async.wait_group %0;" :: "n"(N))

__device__ __forceinline__ void ldm_x4(uint32_t* r, uint32_t addr) {
    asm volatile("ldmatrix.sync.aligned.m8n8.x4.shared.b16 {%0,%1,%2,%3}, [%4];"
                 : "=r"(r[0]), "=r"(r[1]), "=r"(r[2]), "=r"(r[3]) : "r"(addr));
}
__device__ __forceinline__ void ldm_x4t(uint32_t* r, uint32_t addr) {
    asm volatile("ldmatrix.sync.aligned.m8n8.x4.trans.shared.b16 {%0,%1,%2,%3}, [%4];"
                 : "=r"(r[0]), "=r"(r[1]), "=r"(r[2]), "=r"(r[3]) : "r"(addr));
}
__device__ __forceinline__ void mma16816(float* d, const uint32_t* a,
                                         uint32_t b0, uint32_t b1) {
    asm volatile(
        "mma.sync.aligned.m16n8k16.row.col.f32.f16.f16.f32 "
        "{%0,%1,%2,%3}, {%4,%5,%6,%7}, {%8,%9}, {%0,%1,%2,%3};"
        : "+f"(d[0]), "+f"(d[1]), "+f"(d[2]), "+f"(d[3])
        : "r"(a[0]), "r"(a[1]), "r"(a[2]), "r"(a[3]), "r"(b0), "r"(b1));
}
__device__ __forceinline__ float ex2(float x) {
    float r;
    asm("ex2.approx.f32 %0, %1;" : "=f"(r) : "f"(x));
    return r;
}

// ---------------------------------------------------------------------------
// fp32 -> fp16 converts
// ---------------------------------------------------------------------------
__global__ __launch_bounds__(256) void f2h_kernel(
    const float* __restrict__ in, __half* __restrict__ out, int n8)
{
    int i = blockIdx.x * blockDim.x + threadIdx.x;
    if (i >= n8) return;
    float4 v0 = ((const float4*)in)[2 * i];
    float4 v1 = ((const float4*)in)[2 * i + 1];
    __half2 h[4];
    h[0] = __floats2half2_rn(v0.x, v0.y);
    h[1] = __floats2half2_rn(v0.z, v0.w);
    h[2] = __floats2half2_rn(v1.x, v1.y);
    h[3] = __floats2half2_rn(v1.z, v1.w);
    ((uint4*)out)[i] = *(uint4*)h;
}

__global__ __launch_bounds__(256) void f2h4_kernel(
    const float* __restrict__ w0, const float* __restrict__ w1,
    const float* __restrict__ w2, const float* __restrict__ w3,
    __half* o0, __half* o1, __half* o2, __half* o3)
{
    const int z = blockIdx.z;
    const float* in = (z == 0) ? w0 : (z == 1) ? w1 : (z == 2) ? w2 : w3;
    __half* out = (z == 0) ? o0 : (z == 1) ? o1 : (z == 2) ? o2 : o3;
    int i = blockIdx.x * blockDim.x + threadIdx.x;
    float4 v0 = ((const float4*)in)[2 * i];
    float4 v1 = ((const float4*)in)[2 * i + 1];
    __half2 h[4];
    h[0] = __floats2half2_rn(v0.x, v0.y);
    h[1] = __floats2half2_rn(v0.z, v0.w);
    h[2] = __floats2half2_rn(v1.x, v1.y);
    h[3] = __floats2half2_rn(v1.z, v1.w);
    ((uint4*)out)[i] = *(uint4*)h;
}

// ---------------------------------------------------------------------------
// Persistent fp16 GEMM (R14: R10 mainloop + smem-staged coalesced epilogue).
// ---------------------------------------------------------------------------
#define BM 128
#define BN 128
#define BK 64
#define GSTG 3
#define STG_A (BM * 128)
#define STG_B (BN * 128)
#define STG_BYTES (STG_A + STG_B)            // 32KB
#define EPI_LD 72                             // halves, padded row
#define EPI_WARP_BYTES (16 * EPI_LD * 2)
#define EPI_BYTES (4 * EPI_WARP_BYTES)        // 9216B
#define GEMM_SMEM (GSTG * STG_BYTES + EPI_BYTES)   // 107520B
#define NKT (NC / BK)                         // 16

__global__ __launch_bounds__(128, 2) void hgemm_kernel(
    const __half* __restrict__ A,
    const __half* __restrict__ W0, const __half* __restrict__ W1,
    const __half* __restrict__ W2,
    __half* oh0, __half* oh1, __half* oh2,
    float* ofp, const float* __restrict__ bias,
    int ntot, float zsc)
{
    extern __shared__ char smem[];
    const uint32_t sb = smem_u32(smem);
    const int tid  = threadIdx.x;
    const int wid  = tid >> 5;
    const int lane = tid & 31;
    const int wm   = wid >> 1;
    const int wn   = wid & 1;

    int t_pf = blockIdx.x, kt_pf = 0;
    const char* pf_Ag = nullptr;
    const char* pf_Wg = nullptr;
    if (t_pf < ntot) {
        int z = t_pf >> 9, rm = t_pf & 511;
        const __half* W = (z == 0) ? W0 : (z == 1) ? W1 : W2;
        pf_Ag = (const char*)(A + (size_t)(rm >> 3) * (BM * NC));
        pf_Wg = (const char*)(W + (size_t)(rm & 7) * (BN * NC));
    }

    auto load_stage = [&](int s) {
        if (t_pf >= ntot) return;
        uint32_t base = sb + s * STG_BYTES;
#pragma unroll
        for (int i = 0; i < 8; i++) {
            int idx = i * 128 + tid;
            int row = idx >> 3, c = idx & 7;
            cp16(base + row * 128 + ((c ^ (row & 7)) << 4),
                 pf_Ag + (size_t)row * 2048 + kt_pf * 128 + c * 16);
        }
#pragma unroll
        for (int i = 0; i < 8; i++) {
            int idx = i * 128 + tid;
            int row = idx >> 3, c = idx & 7;
            cp16(base + STG_A + row * 128 + ((c ^ (row & 7)) << 4),
                 pf_Wg + (size_t)row * 2048 + kt_pf * 128 + c * 16);
        }
    };
    auto advance_pf = [&]() {
        if (++kt_pf == NKT) {
            kt_pf = 0;
            t_pf += gridDim.x;
            if (t_pf < ntot) {
                int z = t_pf >> 9, rm = t_pf & 511;
                const __half* W = (z == 0) ? W0 : (z == 1) ? W1 : W2;
                pf_Ag = (const char*)(A + (size_t)(rm >> 3) * (BM * NC));
                pf_Wg = (const char*)(W + (size_t)(rm & 7) * (BN * NC));
            }
        }
    };

    load_stage(0); CP_COMMIT(); advance_pf();
    load_stage(1); CP_COMMIT(); advance_pf();

    const int g  = lane >> 3;
    const int gi = lane & 7;
    int buf = 0;

    __half* ep = (__half*)(smem + GSTG * STG_BYTES) + wid * 16 * EPI_LD;

    for (int t = blockIdx.x; t < ntot; t += gridDim.x) {
        float acc[4][8][4];
#pragma unroll
        for (int i = 0; i < 4; i++)
#pragma unroll
            for (int j = 0; j < 8; j++)
#pragma unroll
                for (int e = 0; e < 4; e++) acc[i][j][e] = 0.0f;

        for (int kt = 0; kt < NKT; kt++) {
            CP_WAIT(1);
            __syncthreads();
            load_stage((buf == 0) ? 2 : buf - 1);
            CP_COMMIT();
            advance_pf();

            uint32_t abase = sb + buf * STG_BYTES;
            uint32_t bbase = abase + STG_A;
#pragma unroll
            for (int ks = 0; ks < 4; ks++) {
                uint32_t afr[4][4];
#pragma unroll
                for (int mi = 0; mi < 4; mi++) {
                    int row = wm * 64 + mi * 16 + (g & 1) * 8 + gi;
                    int kc  = ks * 2 + (g >> 1);
                    ldm_x4(afr[mi], abase + row * 128 + ((kc ^ (row & 7)) << 4));
                }
                uint32_t bfr[4][4];
#pragma unroll
                for (int np = 0; np < 4; np++) {
                    int nrow = wn * 64 + np * 16 + (g >> 1) * 8 + gi;
                    int kc   = ks * 2 + (g & 1);
                    ldm_x4(bfr[np], bbase + nrow * 128 + ((kc ^ (nrow & 7)) << 4));
                }
#pragma unroll
                for (int mi = 0; mi < 4; mi++)
#pragma unroll
                    for (int np = 0; np < 4; np++)
#pragma unroll
                        for (int j = 0; j < 2; j++)
                            mma16816(acc[mi][np * 2 + j], afr[mi],
                                     bfr[np][2 * j], bfr[np][2 * j + 1]);
            }
            buf = (buf == 2) ? 0 : buf + 1;
        }

        const int z  = t >> 9, rm = t & 511;
        const int m0 = (rm >> 3) * BM;
        const int n0 = (rm & 7) * BN;
        const int r0c = lane >> 2;
        const int cc  = (lane & 3) * 2;

        if (ofp) {
#pragma unroll
            for (int mi = 0; mi < 4; mi++) {
#pragma unroll
                for (int ni = 0; ni < 8; ni++) {
                    int row = m0 + wm * 64 + mi * 16 + r0c;
                    int col = n0 + wn * 64 + ni * 8 + cc;
                    float* a = acc[mi][ni];
                    float2 b2 = *(const float2*)&bias[col];
                    *(float2*)&ofp[(size_t)row * NC + col] =
                        make_float2(a[0] + b2.x, a[1] + b2.y);
                    *(float2*)&ofp[(size_t)(row + 8) * NC + col] =
                        make_float2(a[2] + b2.x, a[3] + b2.y);
                }
            }
        } else {
            __half* oh = (z == 0) ? oh0 : (z == 1) ? oh1 : oh2;
            const float sc = (z == 0) ? zsc : 1.0f;
            const int rr  = lane >> 3;
            const int ch  = (lane & 7) * 8;
#pragma unroll
            for (int mi = 0; mi < 4; mi++) {
#pragma unroll
                for (int ni = 0; ni < 8; ni++) {
                    float* a = acc[mi][ni];
                    __half2 h0 = __floats2half2_rn(a[0] * sc, a[1] * sc);
                    __half2 h1 = __floats2half2_rn(a[2] * sc, a[3] * sc);
                    *(__half2*)&ep[r0c * EPI_LD + ni * 8 + cc] = h0;
                    *(__half2*)&ep[(r0c + 8) * EPI_LD + ni * 8 + cc] = h1;
                }
                __syncwarp();
#pragma unroll
                for (int p = 0; p < 4; p++) {
                    int row = p * 4 + rr;
                    uint4 vdat = *(uint4*)&ep[row * EPI_LD + ch];
                    int grow = m0 + wm * 64 + mi * 16 + row;
                    *(uint4*)&oh[(size_t)grow * NC + n0 + wn * 64 + ch] = vdat;
                }
                __syncwarp();
            }
        }
    }
}

// ---------------------------------------------------------------------------
// Attention (R13 proven config): BI=128, 4 warps x 32 key rows, 2 CTAs/SM,
// BJ=64 jt tiles, 3-buffer pipeline (CP_WAIT(1) overlap), jj-granular
// strips, K pre-scaled, p = ex2(s). Unmasked body + 2-iter masked tail.
// ---------------------------------------------------------------------------
#define BI 128
#define BJ 64
#define LDH 72
#define ATT_SMEM ((BI + 6 * BJ) * LDH * 2)   // 73728 bytes

__global__ __launch_bounds__(128, 2) void attn_kernel(
    const __half* __restrict__ q, const __half* __restrict__ k,
    const __half* __restrict__ v, __half* __restrict__ y)
{
    extern __shared__ char smraw[];
    __half* Ks = (__half*)smraw;
    __half* Qs = Ks + BI * LDH;
    __half* Vs = Qs + 3 * BJ * LDH;

    const int bh = blockIdx.x;
    const int b  = bh >> 4;
    const int h  = bh & 15;
    const int it = (int)(gridDim.y - 1) - (int)blockIdx.y;
    const int i0 = it * BI;
    const int jt_max = 2 * it + 1;
    const int tid  = threadIdx.x;
    const int wid  = tid >> 5;
    const int lane = tid & 31;

    const __half* qg = q + (size_t)b * NT * NC + (size_t)h * ND;
    const __half* kg = k + (size_t)b * NT * NC + (size_t)h * ND;
    const __half* vg = v + (size_t)b * NT * NC + (size_t)h * ND;

    auto load_qv = [&](int jt) {
        int bufq = jt % 3;
        const __half* qsrc = qg + (size_t)(jt * BJ) * NC;
        const __half* vsrc = vg + (size_t)(jt * BJ) * NC;
        __half* qd = Qs + bufq * BJ * LDH;
        __half* vd = Vs + bufq * BJ * LDH;
#pragma unroll
        for (int i = 0; i < 4; i++) {
            int idx = i * 128 + tid;
            int r = idx >> 3, c = idx & 7;
            cp16(smem_u32(&qd[r * LDH + c * 8]), qsrc + (size_t)r * NC + c * 8);
            cp16(smem_u32(&vd[r * LDH + c * 8]), vsrc + (size_t)r * NC + c * 8);
        }
    };

    {
#pragma unroll
        for (int i = 0; i < 8; i++) {
            int idx = i * 128 + tid;
            int r = idx >> 3, c = idx & 7;
            cp16(smem_u32(&Ks[r * LDH + c * 8]),
                 kg + (size_t)(i0 + r) * NC + c * 8);
        }
        load_qv(0);
        CP_COMMIT();
        load_qv(1);
        CP_COMMIT();
    }

    const int ilocal = wid * 32;

    float yacc[2][8][4];
    float dsum[2][2];
    uint32_t ka[2][4][4];
#pragma unroll
    for (int mi = 0; mi < 2; mi++) {
        dsum[mi][0] = dsum[mi][1] = 0.0f;
#pragma unroll
        for (int f = 0; f < 8; f++)
#pragma unroll
            for (int e = 0; e < 4; e++) yacc[mi][f][e] = 0.0f;
    }

    auto body = [&](int jt, bool need_mask) {
        CP_WAIT(1);
        __syncthreads();
        if (jt + 2 <= jt_max) load_qv(jt + 2);
        CP_COMMIT();

        const __half* qbuf = Qs + (jt % 3) * BJ * LDH;
        const __half* vbuf = Vs + (jt % 3) * BJ * LDH;

        if (jt == 0) {
#pragma unroll
            for (int mi = 0; mi < 2; mi++)
#pragma unroll
                for (int d = 0; d < 4; d++)
                    ldm_x4(ka[mi][d],
                           smem_u32(&Ks[(ilocal + mi * 16 + (lane & 15)) * LDH +
                                        d * 16 + ((lane >> 4) << 3)]));
        }

#pragma unroll
        for (int jj = 0; jj < 4; jj++) {
            float sacc[2][2][4];
#pragma unroll
            for (int mi = 0; mi < 2; mi++)
#pragma unroll
                for (int j = 0; j < 2; j++)
#pragma unroll
                    for (int e = 0; e < 4; e++) sacc[mi][j][e] = 0.0f;

#pragma unroll
            for (int d = 0; d < 4; d++) {
                uint32_t qf[4];
                ldm_x4(qf, smem_u32(&qbuf[(jj * 16 + ((lane >> 4) << 3) +
                                           (lane & 7)) * LDH +
                                          d * 16 + (((lane >> 3) & 1) << 3)]));
#pragma unroll
                for (int mi = 0; mi < 2; mi++) {
                    mma16816(sacc[mi][0], ka[mi][d], qf[0], qf[1]);
                    mma16816(sacc[mi][1], ka[mi][d], qf[2], qf[3]);
                }
            }

            uint32_t pa[2][2][2];
#pragma unroll
            for (int mi = 0; mi < 2; mi++) {
                const int ig0 = i0 + ilocal + mi * 16 + (lane >> 2);
#pragma unroll
                for (int j = 0; j < 2; j++) {
                    const int nt = jj * 2 + j;
                    float p0 = ex2(sacc[mi][j][0]);
                    float p1 = ex2(sacc[mi][j][1]);
                    float p2 = ex2(sacc[mi][j][2]);
                    float p3 = ex2(sacc[mi][j][3]);
                    if (need_mask) {
                        int jg = jt * BJ + nt * 8 + ((lane & 3) << 1);
                        if (jg     > ig0)     p0 = 0.0f;
                        if (jg + 1 > ig0)     p1 = 0.0f;
                        if (jg     > ig0 + 8) p2 = 0.0f;
                        if (jg + 1 > ig0 + 8) p3 = 0.0f;
                    }
                    dsum[mi][0] += p0 + p1;
                    dsum[mi][1] += p2 + p3;
                    __half2 h01 = __floats2half2_rn(p0, p1);
                    __half2 h23 = __floats2half2_rn(p2, p3);
                    pa[mi][j][0] = *(uint32_t*)&h01;
                    pa[mi][j][1] = *(uint32_t*)&h23;
                }
            }

            uint32_t vf[4][4];
#pragma unroll
            for (int dd = 0; dd < 4; dd++)
                ldm_x4t(vf[dd],
                        smem_u32(&vbuf[(jj * 16 + (lane & 15)) * LDH +
                                       dd * 16 + ((lane >> 4) << 3)]));
#pragma unroll
            for (int mi = 0; mi < 2; mi++) {
                uint32_t af[4] = { pa[mi][0][0], pa[mi][0][1],
                                   pa[mi][1][0], pa[mi][1][1] };
#pragma unroll
                for (int dd = 0; dd < 4; dd++) {
                    mma16816(yacc[mi][dd * 2],     af, vf[dd][0], vf[dd][1]);
                    mma16816(yacc[mi][dd * 2 + 1], af, vf[dd][2], vf[dd][3]);
                }
            }
        }
    };

    int jt = 0;
    for (; jt < 2 * it; jt++) body(jt, false);
    for (; jt <= jt_max; jt++) body(jt, true);

    float inv[2][2];
#pragma unroll
    for (int mi = 0; mi < 2; mi++) {
#pragma unroll
        for (int e = 0; e < 2; e++) {
            float s = dsum[mi][e];
            s += __shfl_xor_sync(0xFFFFFFFFu, s, 1);
            s += __shfl_xor_sync(0xFFFFFFFFu, s, 2);
            inv[mi][e] = 1.0f / s;
        }
    }

    {
        int r = lane >> 2, cb = (lane & 3) << 1;
#pragma unroll
        for (int mi = 0; mi < 2; mi++)
#pragma unroll
            for (int nt = 0; nt < 8; nt++) {
                __half2 h0 = __floats2half2_rn(yacc[mi][nt][0] * inv[mi][0],
                                               yacc[mi][nt][1] * inv[mi][0]);
                __half2 h1 = __floats2half2_rn(yacc[mi][nt][2] * inv[mi][1],
                                               yacc[mi][nt][3] * inv[mi][1]);
                *(__half2*)&Ks[(ilocal + mi * 16 + r) * LDH + nt * 8 + cb] = h0;
                *(__half2*)&Ks[(ilocal + mi * 16 + r + 8) * LDH + nt * 8 + cb] = h1;
            }
    }
    __syncthreads();
    {
        __half* yg = y + (size_t)b * NT * NC + (size_t)h * ND;
#pragma unroll
        for (int i = 0; i < 8; i++) {
            int idx = i * 128 + tid;
            int r = idx >> 3, c = idx & 7;
            *(uint4*)&yg[(size_t)(i0 + r) * NC + c * 8] =
                *(uint4*)&Ks[r * LDH + c * 8];
        }
    }
}

// ---------------------------------------------------------------------------
extern "C" void kernel_launch(void* const* d_in, const int* in_sizes, int n_in,
                              void* d_out, int out_size)
{
    const float* x  = (const float*)d_in[0];
    const float* Wk = (const float*)d_in[1];
    const float* Wq = (const float*)d_in[2];
    const float* Wv = (const float*)d_in[3];
    const float* Wp = (const float*)d_in[4];
    const float* bp = (const float*)d_in[5];
    float* out = (float*)d_out;

    __half *qb, *kb, *vb, *yb, *xh, *wk, *wq, *wv, *wp;
    cudaGetSymbolAddress((void**)&qb, g_q);
    cudaGetSymbolAddress((void**)&kb, g_k);
    cudaGetSymbolAddress((void**)&vb, g_v);
    cudaGetSymbolAddress((void**)&yb, g_y);
    cudaGetSymbolAddress((void**)&xh, g_xh);
    cudaGetSymbolAddress((void**)&wk, g_wk);
    cudaGetSymbolAddress((void**)&wq, g_wq);
    cudaGetSymbolAddress((void**)&wv, g_wv);
    cudaGetSymbolAddress((void**)&wp, g_wp);

    int nsm = 148;
    cudaDeviceGetAttribute(&nsm, cudaDevAttrMultiProcessorCount, 0);
    const int pgrid = 2 * nsm;

    f2h_kernel<<<(NM * NC / 8 + 255) / 256, 256>>>(x, xh, NM * NC / 8);
    f2h4_kernel<<<dim3(NC * NC / 8 / 256, 1, 4), 256>>>(
        Wk, Wq, Wv, Wp, wk, wq, wv, wp);

    cudaFuncSetAttribute(hgemm_kernel,
                         cudaFuncAttributeMaxDynamicSharedMemorySize, GEMM_SMEM);

    hgemm_kernel<<<pgrid, 128, GEMM_SMEM>>>(
        xh, wk, wq, wv, kb, qb, vb, nullptr, nullptr, 1536, KSCALE);

    cudaFuncSetAttribute(attn_kernel,
                         cudaFuncAttributeMaxDynamicSharedMemorySize, ATT_SMEM);
    attn_kernel<<<dim3(NB * NH, NT / BI), 128, ATT_SMEM>>>(qb, kb, vb, yb);

    hgemm_kernel<<<pgrid, 128, GEMM_SMEM>>>(
        yb, wp, wp, wp, nullptr, nullptr, nullptr, out, bp, 512, 1.0f);
}

// round 16
// speedup vs baseline: 1.0377x; 1.0132x over previous
#include <cuda_runtime.h>
#include <cuda_fp16.h>
#include <mma.h>
#include <cstdint>
using namespace nvcuda;

#define NB 8
#define NT 1024
#define NC 1024
#define NH 16
#define ND 64
#define NM (NB * NT)   // 8192

// K pre-scale: D^-0.5 * log2(e), folded into K so softmax is a bare exp2
#define KSCALE 0.1803368801111204f

// Scratch (device globals; fp16 activations)
__device__ __half g_q[NM * NC];
__device__ __half g_k[NM * NC];
__device__ __half g_v[NM * NC];
__device__ __half g_y[NM * NC];
__device__ __half g_xh[NM * NC];
__device__ __half g_wk[NC * NC];
__device__ __half g_wq[NC * NC];
__device__ __half g_wv[NC * NC];
__device__ __half g_wp[NC * NC];

// ---------------------------------------------------------------------------
// helpers
// ---------------------------------------------------------------------------
__device__ __forceinline__ uint32_t smem_u32(const void* p) {
    uint32_t a;
    asm("{ .reg .u64 t; cvta.to.shared.u64 t, %1; cvt.u32.u64 %0, t; }"
        : "=r"(a) : "l"(p));
    return a;
}
__device__ __forceinline__ void cp16(uint32_t dst, const void* src) {
    asm volatile("cp.async.cg.shared.global [%0], [%1], 16;"
                 :: "r"(dst), "l"(src));
}
#define CP_COMMIT() asm volatile("cp.async.commit_group;")
#define CP_WAIT(N)  asm volatile("cp.async.wait_group %0;" :: "n"(N))

__device__ __forceinline__ void ldm_x4(uint32_t* r, uint32_t addr) {
    asm volatile("ldmatrix.sync.aligned.m8n8.x4.shared.b16 {%0,%1,%2,%3}, [%4];"
                 : "=r"(r[0]), "=r"(r[1]), "=r"(r[2]), "=r"(r[3]) : "r"(addr));
}
__device__ __forceinline__ void ldm_x4t(uint32_t* r, uint32_t addr) {
    asm volatile("ldmatrix.sync.aligned.m8n8.x4.trans.shared.b16 {%0,%1,%2,%3}, [%4];"
                 : "=r"(r[0]), "=r"(r[1]), "=r"(r[2]), "=r"(r[3]) : "r"(addr));
}
__device__ __forceinline__ void mma16816(float* d, const uint32_t* a,
                                         uint32_t b0, uint32_t b1) {
    asm volatile(
        "mma.sync.aligned.m16n8k16.row.col.f32.f16.f16.f32 "
        "{%0,%1,%2,%3}, {%4,%5,%6,%7}, {%8,%9}, {%0,%1,%2,%3};"
        : "+f"(d[0]), "+f"(d[1]), "+f"(d[2]), "+f"(d[3])
        : "r"(a[0]), "r"(a[1]), "r"(a[2]), "r"(a[3]), "r"(b0), "r"(b1));
}
__device__ __forceinline__ float ex2(float x) {
    float r;
    asm("ex2.approx.f32 %0, %1;" : "=f"(r) : "f"(x));
    return r;
}

// ---------------------------------------------------------------------------
// Single fused fp32 -> fp16 convert: x (1M chunks) + 4 weights (128K each).
// One launch, flat uint4-chunk indexing.
// ---------------------------------------------------------------------------
#define XCHUNKS (NM * NC / 8)          // 1048576
#define WCHUNKS (NC * NC / 8)          // 131072
#define ALLCHUNKS (XCHUNKS + 4 * WCHUNKS)

__global__ __launch_bounds__(256) void f2h_all_kernel(
    const float* __restrict__ x,
    const float* __restrict__ w0, const float* __restrict__ w1,
    const float* __restrict__ w2, const float* __restrict__ w3,
    __half* ox, __half* o0, __half* o1, __half* o2, __half* o3)
{
    int idx = blockIdx.x * 256 + threadIdx.x;
    const float* in;
    __half* out;
    int off;
    if (idx < XCHUNKS) {
        in = x; out = ox; off = idx;
    } else {
        int r = idx - XCHUNKS;
        int w = r >> 17;               // WCHUNKS = 2^17
        off = r & (WCHUNKS - 1);
        in  = (w == 0) ? w0 : (w == 1) ? w1 : (w == 2) ? w2 : w3;
        out = (w == 0) ? o0 : (w == 1) ? o1 : (w == 2) ? o2 : o3;
    }
    float4 v0 = ((const float4*)in)[2 * off];
    float4 v1 = ((const float4*)in)[2 * off + 1];
    __half2 h[4];
    h[0] = __floats2half2_rn(v0.x, v0.y);
    h[1] = __floats2half2_rn(v0.z, v0.w);
    h[2] = __floats2half2_rn(v1.x, v1.y);
    h[3] = __floats2half2_rn(v1.z, v1.w);
    ((uint4*)out)[off] = *(uint4*)h;
}

// ---------------------------------------------------------------------------
// Persistent fp16 GEMM (R15: R10 mainloop + smem-staged coalesced epilogue).
// ---------------------------------------------------------------------------
#define BM 128
#define BN 128
#define BK 64
#define GSTG 3
#define STG_A (BM * 128)
#define STG_B (BN * 128)
#define STG_BYTES (STG_A + STG_B)            // 32KB
#define EPI_LD 72
#define EPI_WARP_BYTES (16 * EPI_LD * 2)
#define EPI_BYTES (4 * EPI_WARP_BYTES)        // 9216B
#define GEMM_SMEM (GSTG * STG_BYTES + EPI_BYTES)   // 107520B
#define NKT (NC / BK)                         // 16

__global__ __launch_bounds__(128, 2) void hgemm_kernel(
    const __half* __restrict__ A,
    const __half* __restrict__ W0, const __half* __restrict__ W1,
    const __half* __restrict__ W2,
    __half* oh0, __half* oh1, __half* oh2,
    float* ofp, const float* __restrict__ bias,
    int ntot, float zsc)
{
    extern __shared__ char smem[];
    const uint32_t sb = smem_u32(smem);
    const int tid  = threadIdx.x;
    const int wid  = tid >> 5;
    const int lane = tid & 31;
    const int wm   = wid >> 1;
    const int wn   = wid & 1;

    int t_pf = blockIdx.x, kt_pf = 0;
    const char* pf_Ag = nullptr;
    const char* pf_Wg = nullptr;
    if (t_pf < ntot) {
        int z = t_pf >> 9, rm = t_pf & 511;
        const __half* W = (z == 0) ? W0 : (z == 1) ? W1 : W2;
        pf_Ag = (const char*)(A + (size_t)(rm >> 3) * (BM * NC));
        pf_Wg = (const char*)(W + (size_t)(rm & 7) * (BN * NC));
    }

    auto load_stage = [&](int s) {
        if (t_pf >= ntot) return;
        uint32_t base = sb + s * STG_BYTES;
#pragma unroll
        for (int i = 0; i < 8; i++) {
            int idx = i * 128 + tid;
            int row = idx >> 3, c = idx & 7;
            cp16(base + row * 128 + ((c ^ (row & 7)) << 4),
                 pf_Ag + (size_t)row * 2048 + kt_pf * 128 + c * 16);
        }
#pragma unroll
        for (int i = 0; i < 8; i++) {
            int idx = i * 128 + tid;
            int row = idx >> 3, c = idx & 7;
            cp16(base + STG_A + row * 128 + ((c ^ (row & 7)) << 4),
                 pf_Wg + (size_t)row * 2048 + kt_pf * 128 + c * 16);
        }
    };
    auto advance_pf = [&]() {
        if (++kt_pf == NKT) {
            kt_pf = 0;
            t_pf += gridDim.x;
            if (t_pf < ntot) {
                int z = t_pf >> 9, rm = t_pf & 511;
                const __half* W = (z == 0) ? W0 : (z == 1) ? W1 : W2;
                pf_Ag = (const char*)(A + (size_t)(rm >> 3) * (BM * NC));
                pf_Wg = (const char*)(W + (size_t)(rm & 7) * (BN * NC));
            }
        }
    };

    load_stage(0); CP_COMMIT(); advance_pf();
    load_stage(1); CP_COMMIT(); advance_pf();

    const int g  = lane >> 3;
    const int gi = lane & 7;
    int buf = 0;

    __half* ep = (__half*)(smem + GSTG * STG_BYTES) + wid * 16 * EPI_LD;

    for (int t = blockIdx.x; t < ntot; t += gridDim.x) {
        float acc[4][8][4];
#pragma unroll
        for (int i = 0; i < 4; i++)
#pragma unroll
            for (int j = 0; j < 8; j++)
#pragma unroll
                for (int e = 0; e < 4; e++) acc[i][j][e] = 0.0f;

        for (int kt = 0; kt < NKT; kt++) {
            CP_WAIT(1);
            __syncthreads();
            load_stage((buf == 0) ? 2 : buf - 1);
            CP_COMMIT();
            advance_pf();

            uint32_t abase = sb + buf * STG_BYTES;
            uint32_t bbase = abase + STG_A;
#pragma unroll
            for (int ks = 0; ks < 4; ks++) {
                uint32_t afr[4][4];
#pragma unroll
                for (int mi = 0; mi < 4; mi++) {
                    int row = wm * 64 + mi * 16 + (g & 1) * 8 + gi;
                    int kc  = ks * 2 + (g >> 1);
                    ldm_x4(afr[mi], abase + row * 128 + ((kc ^ (row & 7)) << 4));
                }
                uint32_t bfr[4][4];
#pragma unroll
                for (int np = 0; np < 4; np++) {
                    int nrow = wn * 64 + np * 16 + (g >> 1) * 8 + gi;
                    int kc   = ks * 2 + (g & 1);
                    ldm_x4(bfr[np], bbase + nrow * 128 + ((kc ^ (nrow & 7)) << 4));
                }
#pragma unroll
                for (int mi = 0; mi < 4; mi++)
#pragma unroll
                    for (int np = 0; np < 4; np++)
#pragma unroll
                        for (int j = 0; j < 2; j++)
                            mma16816(acc[mi][np * 2 + j], afr[mi],
                                     bfr[np][2 * j], bfr[np][2 * j + 1]);
            }
            buf = (buf == 2) ? 0 : buf + 1;
        }

        const int z  = t >> 9, rm = t & 511;
        const int m0 = (rm >> 3) * BM;
        const int n0 = (rm & 7) * BN;
        const int r0c = lane >> 2;
        const int cc  = (lane & 3) * 2;

        if (ofp) {
#pragma unroll
            for (int mi = 0; mi < 4; mi++) {
#pragma unroll
                for (int ni = 0; ni < 8; ni++) {
                    int row = m0 + wm * 64 + mi * 16 + r0c;
                    int col = n0 + wn * 64 + ni * 8 + cc;
                    float* a = acc[mi][ni];
                    float2 b2 = *(const float2*)&bias[col];
                    *(float2*)&ofp[(size_t)row * NC + col] =
                        make_float2(a[0] + b2.x, a[1] + b2.y);
                    *(float2*)&ofp[(size_t)(row + 8) * NC + col] =
                        make_float2(a[2] + b2.x, a[3] + b2.y);
                }
            }
        } else {
            __half* oh = (z == 0) ? oh0 : (z == 1) ? oh1 : oh2;
            const float sc = (z == 0) ? zsc : 1.0f;
            const int rr  = lane >> 3;
            const int ch  = (lane & 7) * 8;
#pragma unroll
            for (int mi = 0; mi < 4; mi++) {
#pragma unroll
                for (int ni = 0; ni < 8; ni++) {
                    float* a = acc[mi][ni];
                    __half2 h0 = __floats2half2_rn(a[0] * sc, a[1] * sc);
                    __half2 h1 = __floats2half2_rn(a[2] * sc, a[3] * sc);
                    *(__half2*)&ep[r0c * EPI_LD + ni * 8 + cc] = h0;
                    *(__half2*)&ep[(r0c + 8) * EPI_LD + ni * 8 + cc] = h1;
                }
                __syncwarp();
#pragma unroll
                for (int p = 0; p < 4; p++) {
                    int row = p * 4 + rr;
                    uint4 vdat = *(uint4*)&ep[row * EPI_LD + ch];
                    int grow = m0 + wm * 64 + mi * 16 + row;
                    *(uint4*)&oh[(size_t)grow * NC + n0 + wn * 64 + ch] = vdat;
                }
                __syncwarp();
            }
        }
    }
}

// ---------------------------------------------------------------------------
// Attention (R15 proven): BI=128, 4 warps x 32 key rows, 2 CTAs/SM,
// BJ=64 jt tiles, 3-buffer pipeline, jj-granular strips, p = ex2(s).
// ---------------------------------------------------------------------------
#define BI 128
#define BJ 64
#define LDH 72
#define ATT_SMEM ((BI + 6 * BJ) * LDH * 2)   // 73728 bytes

__global__ __launch_bounds__(128, 2) void attn_kernel(
    const __half* __restrict__ q, const __half* __restrict__ k,
    const __half* __restrict__ v, __half* __restrict__ y)
{
    extern __shared__ char smraw[];
    __half* Ks = (__half*)smraw;
    __half* Qs = Ks + BI * LDH;
    __half* Vs = Qs + 3 * BJ * LDH;

    const int bh = blockIdx.x;
    const int b  = bh >> 4;
    const int h  = bh & 15;
    const int it = (int)(gridDim.y - 1) - (int)blockIdx.y;
    const int i0 = it * BI;
    const int jt_max = 2 * it + 1;
    const int tid  = threadIdx.x;
    const int wid  = tid >> 5;
    const int lane = tid & 31;

    const __half* qg = q + (size_t)b * NT * NC + (size_t)h * ND;
    const __half* kg = k + (size_t)b * NT * NC + (size_t)h * ND;
    const __half* vg = v + (size_t)b * NT * NC + (size_t)h * ND;

    auto load_qv = [&](int jt) {
        int bufq = jt % 3;
        const __half* qsrc = qg + (size_t)(jt * BJ) * NC;
        const __half* vsrc = vg + (size_t)(jt * BJ) * NC;
        __half* qd = Qs + bufq * BJ * LDH;
        __half* vd = Vs + bufq * BJ * LDH;
#pragma unroll
        for (int i = 0; i < 4; i++) {
            int idx = i * 128 + tid;
            int r = idx >> 3, c = idx & 7;
            cp16(smem_u32(&qd[r * LDH + c * 8]), qsrc + (size_t)r * NC + c * 8);
            cp16(smem_u32(&vd[r * LDH + c * 8]), vsrc + (size_t)r * NC + c * 8);
        }
    };

    {
#pragma unroll
        for (int i = 0; i < 8; i++) {
            int idx = i * 128 + tid;
            int r = idx >> 3, c = idx & 7;
            cp16(smem_u32(&Ks[r * LDH + c * 8]),
                 kg + (size_t)(i0 + r) * NC + c * 8);
        }
        load_qv(0);
        CP_COMMIT();
        load_qv(1);
        CP_COMMIT();
    }

    const int ilocal = wid * 32;

    float yacc[2][8][4];
    float dsum[2][2];
    uint32_t ka[2][4][4];
#pragma unroll
    for (int mi = 0; mi < 2; mi++) {
        dsum[mi][0] = dsum[mi][1] = 0.0f;
#pragma unroll
        for (int f = 0; f < 8; f++)
#pragma unroll
            for (int e = 0; e < 4; e++) yacc[mi][f][e] = 0.0f;
    }

    auto body = [&](int jt, bool need_mask) {
        CP_WAIT(1);
        __syncthreads();
        if (jt + 2 <= jt_max) load_qv(jt + 2);
        CP_COMMIT();

        const __half* qbuf = Qs + (jt % 3) * BJ * LDH;
        const __half* vbuf = Vs + (jt % 3) * BJ * LDH;

        if (jt == 0) {
#pragma unroll
            for (int mi = 0; mi < 2; mi++)
#pragma unroll
                for (int d = 0; d < 4; d++)
                    ldm_x4(ka[mi][d],
                           smem_u32(&Ks[(ilocal + mi * 16 + (lane & 15)) * LDH +
                                        d * 16 + ((lane >> 4) << 3)]));
        }

#pragma unroll
        for (int jj = 0; jj < 4; jj++) {
            float sacc[2][2][4];
#pragma unroll
            for (int mi = 0; mi < 2; mi++)
#pragma unroll
                for (int j = 0; j < 2; j++)
#pragma unroll
                    for (int e = 0; e < 4; e++) sacc[mi][j][e] = 0.0f;

#pragma unroll
            for (int d = 0; d < 4; d++) {
                uint32_t qf[4];
                ldm_x4(qf, smem_u32(&qbuf[(jj * 16 + ((lane >> 4) << 3) +
                                           (lane & 7)) * LDH +
                                          d * 16 + (((lane >> 3) & 1) << 3)]));
#pragma unroll
                for (int mi = 0; mi < 2; mi++) {
                    mma16816(sacc[mi][0], ka[mi][d], qf[0], qf[1]);
                    mma16816(sacc[mi][1], ka[mi][d], qf[2], qf[3]);
                }
            }

            uint32_t pa[2][2][2];
#pragma unroll
            for (int mi = 0; mi < 2; mi++) {
                const int ig0 = i0 + ilocal + mi * 16 + (lane >> 2);
#pragma unroll
                for (int j = 0; j < 2; j++) {
                    const int nt = jj * 2 + j;
                    float p0 = ex2(sacc[mi][j][0]);
                    float p1 = ex2(sacc[mi][j][1]);
                    float p2 = ex2(sacc[mi][j][2]);
                    float p3 = ex2(sacc[mi][j][3]);
                    if (need_mask) {
                        int jg = jt * BJ + nt * 8 + ((lane & 3) << 1);
                        if (jg     > ig0)     p0 = 0.0f;
                        if (jg + 1 > ig0)     p1 = 0.0f;
                        if (jg     > ig0 + 8) p2 = 0.0f;
                        if (jg + 1 > ig0 + 8) p3 = 0.0f;
                    }
                    dsum[mi][0] += p0 + p1;
                    dsum[mi][1] += p2 + p3;
                    __half2 h01 = __floats2half2_rn(p0, p1);
                    __half2 h23 = __floats2half2_rn(p2, p3);
                    pa[mi][j][0] = *(uint32_t*)&h01;
                    pa[mi][j][1] = *(uint32_t*)&h23;
                }
            }

            uint32_t vf[4][4];
#pragma unroll
            for (int dd = 0; dd < 4; dd++)
                ldm_x4t(vf[dd],
                        smem_u32(&vbuf[(jj * 16 + (lane & 15)) * LDH +
                                       dd * 16 + ((lane >> 4) << 3)]));
#pragma unroll
            for (int mi = 0; mi < 2; mi++) {
                uint32_t af[4] = { pa[mi][0][0], pa[mi][0][1],
                                   pa[mi][1][0], pa[mi][1][1] };
#pragma unroll
                for (int dd = 0; dd < 4; dd++) {
                    mma16816(yacc[mi][dd * 2],     af, vf[dd][0], vf[dd][1]);
                    mma16816(yacc[mi][dd * 2 + 1], af, vf[dd][2], vf[dd][3]);
                }
            }
        }
    };

    int jt = 0;
    for (; jt < 2 * it; jt++) body(jt, false);
    for (; jt <= jt_max; jt++) body(jt, true);

    float inv[2][2];
#pragma unroll
    for (int mi = 0; mi < 2; mi++) {
#pragma unroll
        for (int e = 0; e < 2; e++) {
            float s = dsum[mi][e];
            s += __shfl_xor_sync(0xFFFFFFFFu, s, 1);
            s += __shfl_xor_sync(0xFFFFFFFFu, s, 2);
            inv[mi][e] = 1.0f / s;
        }
    }

    {
        int r = lane >> 2, cb = (lane & 3) << 1;
#pragma unroll
        for (int mi = 0; mi < 2; mi++)
#pragma unroll
            for (int nt = 0; nt < 8; nt++) {
                __half2 h0 = __floats2half2_rn(yacc[mi][nt][0] * inv[mi][0],
                                               yacc[mi][nt][1] * inv[mi][0]);
                __half2 h1 = __floats2half2_rn(yacc[mi][nt][2] * inv[mi][1],
                                               yacc[mi][nt][3] * inv[mi][1]);
                *(__half2*)&Ks[(ilocal + mi * 16 + r) * LDH + nt * 8 + cb] = h0;
                *(__half2*)&Ks[(ilocal + mi * 16 + r + 8) * LDH + nt * 8 + cb] = h1;
            }
    }
    __syncthreads();
    {
        __half* yg = y + (size_t)b * NT * NC + (size_t)h * ND;
#pragma unroll
        for (int i = 0; i < 8; i++) {
            int idx = i * 128 + tid;
            int r = idx >> 3, c = idx & 7;
            *(uint4*)&yg[(size_t)(i0 + r) * NC + c * 8] =
                *(uint4*)&Ks[r * LDH + c * 8];
        }
    }
}

// ---------------------------------------------------------------------------
extern "C" void kernel_launch(void* const* d_in, const int* in_sizes, int n_in,
                              void* d_out, int out_size)
{
    const float* x  = (const float*)d_in[0];
    const float* Wk = (const float*)d_in[1];
    const float* Wq = (const float*)d_in[2];
    const float* Wv = (const float*)d_in[3];
    const float* Wp = (const float*)d_in[4];
    const float* bp = (const float*)d_in[5];
    float* out = (float*)d_out;

    __half *qb, *kb, *vb, *yb, *xh, *wk, *wq, *wv, *wp;
    cudaGetSymbolAddress((void**)&qb, g_q);
    cudaGetSymbolAddress((void**)&kb, g_k);
    cudaGetSymbolAddress((void**)&vb, g_v);
    cudaGetSymbolAddress((void**)&yb, g_y);
    cudaGetSymbolAddress((void**)&xh, g_xh);
    cudaGetSymbolAddress((void**)&wk, g_wk);
    cudaGetSymbolAddress((void**)&wq, g_wq);
    cudaGetSymbolAddress((void**)&wv, g_wv);
    cudaGetSymbolAddress((void**)&wp, g_wp);

    int nsm = 148;
    cudaDeviceGetAttribute(&nsm, cudaDevAttrMultiProcessorCount, 0);
    const int pgrid = 2 * nsm;

    // All fp32->fp16 conversions in ONE launch
    f2h_all_kernel<<<ALLCHUNKS / 256, 256>>>(
        x, Wk, Wq, Wv, Wp, xh, wk, wq, wv, wp);

    cudaFuncSetAttribute(hgemm_kernel,
                         cudaFuncAttributeMaxDynamicSharedMemorySize, GEMM_SMEM);

    hgemm_kernel<<<pgrid, 128, GEMM_SMEM>>>(
        xh, wk, wq, wv, kb, qb, vb, nullptr, nullptr, 1536, KSCALE);

    cudaFuncSetAttribute(attn_kernel,
                         cudaFuncAttributeMaxDynamicSharedMemorySize, ATT_SMEM);
    attn_kernel<<<dim3(NB * NH, NT / BI), 128, ATT_SMEM>>>(qb, kb, vb, yb);

    hgemm_kernel<<<pgrid, 128, GEMM_SMEM>>>(
        yb, wp, wp, wp, nullptr, nullptr, nullptr, out, bp, 512, 1.0f);
}

// round 17
// speedup vs baseline: 1.0433x; 1.0054x over previous
#include <cuda_runtime.h>
#include <cuda_fp16.h>
#include <mma.h>
#include <cstdint>
using namespace nvcuda;

#define NB 8
#define NT 1024
#define NC 1024
#define NH 16
#define ND 64
#define NM (NB * NT)   // 8192

#define KSCALE 0.1803368801111204f

__device__ __half g_q[NM * NC];
__device__ __half g_k[NM * NC];
__device__ __half g_v[NM * NC];
__device__ __half g_y[NM * NC];
__device__ __half g_xh[NM * NC];
__device__ __half g_wk[NC * NC];
__device__ __half g_wq[NC * NC];
__device__ __half g_wv[NC * NC];
__device__ __half g_wp[NC * NC];

// ---------------------------------------------------------------------------
// helpers
// ---------------------------------------------------------------------------
__device__ __forceinline__ uint32_t smem_u32(const void* p) {
    uint32_t a;
    asm("{ .reg .u64 t; cvta.to.shared.u64 t, %1; cvt.u32.u64 %0, t; }"
        : "=r"(a) : "l"(p));
    return a;
}
__device__ __forceinline__ void cp16(uint32_t dst, const void* src) {
    asm volatile("cp.async.cg.shared.global [%0], [%1], 16;"
                 :: "r"(dst), "l"(src));
}
#define CP_COMMIT() asm volatile("cp.async.commit_group;")
#define CP_WAIT(N)  asm volatile("cp.async.wait_group %0;" :: "n"(N))

__device__ __forceinline__ void ldm_x4(uint32_t* r, uint32_t addr) {
    asm volatile("ldmatrix.sync.aligned.m8n8.x4.shared.b16 {%0,%1,%2,%3}, [%4];"
                 : "=r"(r[0]), "=r"(r[1]), "=r"(r[2]), "=r"(r[3]) : "r"(addr));
}
__device__ __forceinline__ void ldm_x4t(uint32_t* r, uint32_t addr) {
    asm volatile("ldmatrix.sync.aligned.m8n8.x4.trans.shared.b16 {%0,%1,%2,%3}, [%4];"
                 : "=r"(r[0]), "=r"(r[1]), "=r"(r[2]), "=r"(r[3]) : "r"(addr));
}
__device__ __forceinline__ void mma16816(float* d, const uint32_t* a,
                                         uint32_t b0, uint32_t b1) {
    asm volatile(
        "mma.sync.aligned.m16n8k16.row.col.f32.f16.f16.f32 "
        "{%0,%1,%2,%3}, {%4,%5,%6,%7}, {%8,%9}, {%0,%1,%2,%3};"
        : "+f"(d[0]), "+f"(d[1]), "+f"(d[2]), "+f"(d[3])
        : "r"(a[0]), "r"(a[1]), "r"(a[2]), "r"(a[3]), "r"(b0), "r"(b1));
}
__device__ __forceinline__ float ex2(float x) {
    float r;
    asm("ex2.approx.f32 %0, %1;" : "=f"(r) : "f"(x));
    return r;
}

// ---------------------------------------------------------------------------
// Single fused fp32 -> fp16 convert (R16)
// ---------------------------------------------------------------------------
#define XCHUNKS (NM * NC / 8)
#define WCHUNKS (NC * NC / 8)
#define ALLCHUNKS (XCHUNKS + 4 * WCHUNKS)

__global__ __launch_bounds__(256) void f2h_all_kernel(
    const float* __restrict__ x,
    const float* __restrict__ w0, const float* __restrict__ w1,
    const float* __restrict__ w2, const float* __restrict__ w3,
    __half* ox, __half* o0, __half* o1, __half* o2, __half* o3)
{
    int idx = blockIdx.x * 256 + threadIdx.x;
    const float* in;
    __half* out;
    int off;
    if (idx < XCHUNKS) {
        in = x; out = ox; off = idx;
    } else {
        int r = idx - XCHUNKS;
        int w = r >> 17;
        off = r & (WCHUNKS - 1);
        in  = (w == 0) ? w0 : (w == 1) ? w1 : (w == 2) ? w2 : w3;
        out = (w == 0) ? o0 : (w == 1) ? o1 : (w == 2) ? o2 : o3;
    }
    float4 v0 = ((const float4*)in)[2 * off];
    float4 v1 = ((const float4*)in)[2 * off + 1];
    __half2 h[4];
    h[0] = __floats2half2_rn(v0.x, v0.y);
    h[1] = __floats2half2_rn(v0.z, v0.w);
    h[2] = __floats2half2_rn(v1.x, v1.y);
    h[3] = __floats2half2_rn(v1.z, v1.w);
    ((uint4*)out)[off] = *(uint4*)h;
}

// ---------------------------------------------------------------------------
// Persistent fp16 QKV GEMM (R15/R16, unchanged): 128x128x64 tiles.
// ---------------------------------------------------------------------------
#define BM 128
#define BN 128
#define BK 64
#define GSTG 3
#define STG_A (BM * 128)
#define STG_B (BN * 128)
#define STG_BYTES (STG_A + STG_B)
#define EPI_LD 72
#define EPI_BYTES (4 * 16 * EPI_LD * 2)
#define GEMM_SMEM (GSTG * STG_BYTES + EPI_BYTES)
#define NKT (NC / BK)

__global__ __launch_bounds__(128, 2) void hgemm_kernel(
    const __half* __restrict__ A,
    const __half* __restrict__ W0, const __half* __restrict__ W1,
    const __half* __restrict__ W2,
    __half* oh0, __half* oh1, __half* oh2,
    int ntot, float zsc)
{
    extern __shared__ char smem[];
    const uint32_t sb = smem_u32(smem);
    const int tid  = threadIdx.x;
    const int wid  = tid >> 5;
    const int lane = tid & 31;
    const int wm   = wid >> 1;
    const int wn   = wid & 1;

    int t_pf = blockIdx.x, kt_pf = 0;
    const char* pf_Ag = nullptr;
    const char* pf_Wg = nullptr;
    if (t_pf < ntot) {
        int z = t_pf >> 9, rm = t_pf & 511;
        const __half* W = (z == 0) ? W0 : (z == 1) ? W1 : W2;
        pf_Ag = (const char*)(A + (size_t)(rm >> 3) * (BM * NC));
        pf_Wg = (const char*)(W + (size_t)(rm & 7) * (BN * NC));
    }

    auto load_stage = [&](int s) {
        if (t_pf >= ntot) return;
        uint32_t base = sb + s * STG_BYTES;
#pragma unroll
        for (int i = 0; i < 8; i++) {
            int idx = i * 128 + tid;
            int row = idx >> 3, c = idx & 7;
            cp16(base + row * 128 + ((c ^ (row & 7)) << 4),
                 pf_Ag + (size_t)row * 2048 + kt_pf * 128 + c * 16);
        }
#pragma unroll
        for (int i = 0; i < 8; i++) {
            int idx = i * 128 + tid;
            int row = idx >> 3, c = idx & 7;
            cp16(base + STG_A + row * 128 + ((c ^ (row & 7)) << 4),
                 pf_Wg + (size_t)row * 2048 + kt_pf * 128 + c * 16);
        }
    };
    auto advance_pf = [&]() {
        if (++kt_pf == NKT) {
            kt_pf = 0;
            t_pf += gridDim.x;
            if (t_pf < ntot) {
                int z = t_pf >> 9, rm = t_pf & 511;
                const __half* W = (z == 0) ? W0 : (z == 1) ? W1 : W2;
                pf_Ag = (const char*)(A + (size_t)(rm >> 3) * (BM * NC));
                pf_Wg = (const char*)(W + (size_t)(rm & 7) * (BN * NC));
            }
        }
    };

    load_stage(0); CP_COMMIT(); advance_pf();
    load_stage(1); CP_COMMIT(); advance_pf();

    const int g  = lane >> 3;
    const int gi = lane & 7;
    int buf = 0;

    __half* ep = (__half*)(smem + GSTG * STG_BYTES) + wid * 16 * EPI_LD;

    for (int t = blockIdx.x; t < ntot; t += gridDim.x) {
        float acc[4][8][4];
#pragma unroll
        for (int i = 0; i < 4; i++)
#pragma unroll
            for (int j = 0; j < 8; j++)
#pragma unroll
                for (int e = 0; e < 4; e++) acc[i][j][e] = 0.0f;

        for (int kt = 0; kt < NKT; kt++) {
            CP_WAIT(1);
            __syncthreads();
            load_stage((buf == 0) ? 2 : buf - 1);
            CP_COMMIT();
            advance_pf();

            uint32_t abase = sb + buf * STG_BYTES;
            uint32_t bbase = abase + STG_A;
#pragma unroll
            for (int ks = 0; ks < 4; ks++) {
                uint32_t afr[4][4];
#pragma unroll
                for (int mi = 0; mi < 4; mi++) {
                    int row = wm * 64 + mi * 16 + (g & 1) * 8 + gi;
                    int kc  = ks * 2 + (g >> 1);
                    ldm_x4(afr[mi], abase + row * 128 + ((kc ^ (row & 7)) << 4));
                }
                uint32_t bfr[4][4];
#pragma unroll
                for (int np = 0; np < 4; np++) {
                    int nrow = wn * 64 + np * 16 + (g >> 1) * 8 + gi;
                    int kc   = ks * 2 + (g & 1);
                    ldm_x4(bfr[np], bbase + nrow * 128 + ((kc ^ (nrow & 7)) << 4));
                }
#pragma unroll
                for (int mi = 0; mi < 4; mi++)
#pragma unroll
                    for (int np = 0; np < 4; np++)
#pragma unroll
                        for (int j = 0; j < 2; j++)
                            mma16816(acc[mi][np * 2 + j], afr[mi],
                                     bfr[np][2 * j], bfr[np][2 * j + 1]);
            }
            buf = (buf == 2) ? 0 : buf + 1;
        }

        const int z  = t >> 9, rm = t & 511;
        const int m0 = (rm >> 3) * BM;
        const int n0 = (rm & 7) * BN;
        const int r0c = lane >> 2;
        const int cc  = (lane & 3) * 2;

        __half* oh = (z == 0) ? oh0 : (z == 1) ? oh1 : oh2;
        const float sc = (z == 0) ? zsc : 1.0f;
        const int rr  = lane >> 3;
        const int ch  = (lane & 7) * 8;
#pragma unroll
        for (int mi = 0; mi < 4; mi++) {
#pragma unroll
            for (int ni = 0; ni < 8; ni++) {
                float* a = acc[mi][ni];
                __half2 h0 = __floats2half2_rn(a[0] * sc, a[1] * sc);
                __half2 h1 = __floats2half2_rn(a[2] * sc, a[3] * sc);
                *(__half2*)&ep[r0c * EPI_LD + ni * 8 + cc] = h0;
                *(__half2*)&ep[(r0c + 8) * EPI_LD + ni * 8 + cc] = h1;
            }
            __syncwarp();
#pragma unroll
            for (int p = 0; p < 4; p++) {
                int row = p * 4 + rr;
                uint4 vdat = *(uint4*)&ep[row * EPI_LD + ch];
                int grow = m0 + wm * 64 + mi * 16 + row;
                *(uint4*)&oh[(size_t)grow * NC + n0 + wn * 64 + ch] = vdat;
            }
            __syncwarp();
        }
    }
}

// ---------------------------------------------------------------------------
// Final projection GEMM: BN=64 tiles (1024 tiles -> 96% per-SM quantization
// efficiency vs 84% at BN=128). 4 warps (2M x 2N), warp tile 64x32,
// fp32 output + bias. Tile t: m = t>>4, n = t&15.
// ---------------------------------------------------------------------------
#define BN64 64
#define STG64_B (BN64 * 128)                 // 8KB
#define STG64_BYTES (STG_A + STG64_B)        // 24KB
#define GEMM64_SMEM (GSTG * STG64_BYTES)     // 73728

__global__ __launch_bounds__(128, 2) void hgemm_n64_kernel(
    const __half* __restrict__ A, const __half* __restrict__ W,
    float* __restrict__ ofp, const float* __restrict__ bias, int ntot)
{
    extern __shared__ char smem[];
    const uint32_t sb = smem_u32(smem);
    const int tid  = threadIdx.x;
    const int wid  = tid >> 5;
    const int lane = tid & 31;
    const int wm   = wid >> 1;           // 0..1 (M 64)
    const int wn   = wid & 1;            // 0..1 (N 32)

    int t_pf = blockIdx.x, kt_pf = 0;
    const char* pf_Ag = nullptr;
    const char* pf_Wg = nullptr;
    if (t_pf < ntot) {
        pf_Ag = (const char*)(A + (size_t)(t_pf >> 4) * (BM * NC));
        pf_Wg = (const char*)(W + (size_t)(t_pf & 15) * (BN64 * NC));
    }

    auto load_stage = [&](int s) {
        if (t_pf >= ntot) return;
        uint32_t base = sb + s * STG64_BYTES;
#pragma unroll
        for (int i = 0; i < 8; i++) {            // A: 1024 chunks
            int idx = i * 128 + tid;
            int row = idx >> 3, c = idx & 7;
            cp16(base + row * 128 + ((c ^ (row & 7)) << 4),
                 pf_Ag + (size_t)row * 2048 + kt_pf * 128 + c * 16);
        }
#pragma unroll
        for (int i = 0; i < 4; i++) {            // B: 512 chunks
            int idx = i * 128 + tid;
            int row = idx >> 3, c = idx & 7;
            cp16(base + STG_A + row * 128 + ((c ^ (row & 7)) << 4),
                 pf_Wg + (size_t)row * 2048 + kt_pf * 128 + c * 16);
        }
    };
    auto advance_pf = [&]() {
        if (++kt_pf == NKT) {
            kt_pf = 0;
            t_pf += gridDim.x;
            if (t_pf < ntot) {
                pf_Ag = (const char*)(A + (size_t)(t_pf >> 4) * (BM * NC));
                pf_Wg = (const char*)(W + (size_t)(t_pf & 15) * (BN64 * NC));
            }
        }
    };

    load_stage(0); CP_COMMIT(); advance_pf();
    load_stage(1); CP_COMMIT(); advance_pf();

    const int g  = lane >> 3;
    const int gi = lane & 7;
    int buf = 0;

    for (int t = blockIdx.x; t < ntot; t += gridDim.x) {
        float acc[4][4][4];
#pragma unroll
        for (int i = 0; i < 4; i++)
#pragma unroll
            for (int j = 0; j < 4; j++)
#pragma unroll
                for (int e = 0; e < 4; e++) acc[i][j][e] = 0.0f;

        for (int kt = 0; kt < NKT; kt++) {
            CP_WAIT(1);
            __syncthreads();
            load_stage((buf == 0) ? 2 : buf - 1);
            CP_COMMIT();
            advance_pf();

            uint32_t abase = sb + buf * STG64_BYTES;
            uint32_t bbase = abase + STG_A;
#pragma unroll
            for (int ks = 0; ks < 4; ks++) {
                uint32_t afr[4][4];
#pragma unroll
                for (int mi = 0; mi < 4; mi++) {
                    int row = wm * 64 + mi * 16 + (g & 1) * 8 + gi;
                    int kc  = ks * 2 + (g >> 1);
                    ldm_x4(afr[mi], abase + row * 128 + ((kc ^ (row & 7)) << 4));
                }
                uint32_t bfr[2][4];
#pragma unroll
                for (int np = 0; np < 2; np++) {
                    int nrow = wn * 32 + np * 16 + (g >> 1) * 8 + gi;
                    int kc   = ks * 2 + (g & 1);
                    ldm_x4(bfr[np], bbase + nrow * 128 + ((kc ^ (nrow & 7)) << 4));
                }
#pragma unroll
                for (int mi = 0; mi < 4; mi++)
#pragma unroll
                    for (int np = 0; np < 2; np++)
#pragma unroll
                        for (int j = 0; j < 2; j++)
                            mma16816(acc[mi][np * 2 + j], afr[mi],
                                     bfr[np][2 * j], bfr[np][2 * j + 1]);
            }
            buf = (buf == 2) ? 0 : buf + 1;
        }

        const int m0 = (t >> 4) * BM;
        const int n0 = (t & 15) * BN64;
        const int r0c = lane >> 2;
        const int cc  = (lane & 3) * 2;
#pragma unroll
        for (int mi = 0; mi < 4; mi++) {
#pragma unroll
            for (int ni = 0; ni < 4; ni++) {
                int row = m0 + wm * 64 + mi * 16 + r0c;
                int col = n0 + wn * 32 + ni * 8 + cc;
                float* a = acc[mi][ni];
                float2 b2 = *(const float2*)&bias[col];
                *(float2*)&ofp[(size_t)row * NC + col] =
                    make_float2(a[0] + b2.x, a[1] + b2.y);
                *(float2*)&ofp[(size_t)(row + 8) * NC + col] =
                    make_float2(a[2] + b2.x, a[3] + b2.y);
            }
        }
    }
}

// ---------------------------------------------------------------------------
// Attention (R15 proven, unchanged)
// ---------------------------------------------------------------------------
#define BI 128
#define BJ 64
#define LDH 72
#define ATT_SMEM ((BI + 6 * BJ) * LDH * 2)

__global__ __launch_bounds__(128, 2) void attn_kernel(
    const __half* __restrict__ q, const __half* __restrict__ k,
    const __half* __restrict__ v, __half* __restrict__ y)
{
    extern __shared__ char smraw[];
    __half* Ks = (__half*)smraw;
    __half* Qs = Ks + BI * LDH;
    __half* Vs = Qs + 3 * BJ * LDH;

    const int bh = blockIdx.x;
    const int b  = bh >> 4;
    const int h  = bh & 15;
    const int it = (int)(gridDim.y - 1) - (int)blockIdx.y;
    const int i0 = it * BI;
    const int jt_max = 2 * it + 1;
    const int tid  = threadIdx.x;
    const int wid  = tid >> 5;
    const int lane = tid & 31;

    const __half* qg = q + (size_t)b * NT * NC + (size_t)h * ND;
    const __half* kg = k + (size_t)b * NT * NC + (size_t)h * ND;
    const __half* vg = v + (size_t)b * NT * NC + (size_t)h * ND;

    auto load_qv = [&](int jt) {
        int bufq = jt % 3;
        const __half* qsrc = qg + (size_t)(jt * BJ) * NC;
        const __half* vsrc = vg + (size_t)(jt * BJ) * NC;
        __half* qd = Qs + bufq * BJ * LDH;
        __half* vd = Vs + bufq * BJ * LDH;
#pragma unroll
        for (int i = 0; i < 4; i++) {
            int idx = i * 128 + tid;
            int r = idx >> 3, c = idx & 7;
            cp16(smem_u32(&qd[r * LDH + c * 8]), qsrc + (size_t)r * NC + c * 8);
            cp16(smem_u32(&vd[r * LDH + c * 8]), vsrc + (size_t)r * NC + c * 8);
        }
    };

    {
#pragma unroll
        for (int i = 0; i < 8; i++) {
            int idx = i * 128 + tid;
            int r = idx >> 3, c = idx & 7;
            cp16(smem_u32(&Ks[r * LDH + c * 8]),
                 kg + (size_t)(i0 + r) * NC + c * 8);
        }
        load_qv(0);
        CP_COMMIT();
        load_qv(1);
        CP_COMMIT();
    }

    const int ilocal = wid * 32;

    float yacc[2][8][4];
    float dsum[2][2];
    uint32_t ka[2][4][4];
#pragma unroll
    for (int mi = 0; mi < 2; mi++) {
        dsum[mi][0] = dsum[mi][1] = 0.0f;
#pragma unroll
        for (int f = 0; f < 8; f++)
#pragma unroll
            for (int e = 0; e < 4; e++) yacc[mi][f][e] = 0.0f;
    }

    auto body = [&](int jt, bool need_mask) {
        CP_WAIT(1);
        __syncthreads();
        if (jt + 2 <= jt_max) load_qv(jt + 2);
        CP_COMMIT();

        const __half* qbuf = Qs + (jt % 3) * BJ * LDH;
        const __half* vbuf = Vs + (jt % 3) * BJ * LDH;

        if (jt == 0) {
#pragma unroll
            for (int mi = 0; mi < 2; mi++)
#pragma unroll
                for (int d = 0; d < 4; d++)
                    ldm_x4(ka[mi][d],
                           smem_u32(&Ks[(ilocal + mi * 16 + (lane & 15)) * LDH +
                                        d * 16 + ((lane >> 4) << 3)]));
        }

#pragma unroll
        for (int jj = 0; jj < 4; jj++) {
            float sacc[2][2][4];
#pragma unroll
            for (int mi = 0; mi < 2; mi++)
#pragma unroll
                for (int j = 0; j < 2; j++)
#pragma unroll
                    for (int e = 0; e < 4; e++) sacc[mi][j][e] = 0.0f;

#pragma unroll
            for (int d = 0; d < 4; d++) {
                uint32_t qf[4];
                ldm_x4(qf, smem_u32(&qbuf[(jj * 16 + ((lane >> 4) << 3) +
                                           (lane & 7)) * LDH +
                                          d * 16 + (((lane >> 3) & 1) << 3)]));
#pragma unroll
                for (int mi = 0; mi < 2; mi++) {
                    mma16816(sacc[mi][0], ka[mi][d], qf[0], qf[1]);
                    mma16816(sacc[mi][1], ka[mi][d], qf[2], qf[3]);
                }
            }

            uint32_t pa[2][2][2];
#pragma unroll
            for (int mi = 0; mi < 2; mi++) {
                const int ig0 = i0 + ilocal + mi * 16 + (lane >> 2);
#pragma unroll
                for (int j = 0; j < 2; j++) {
                    const int nt = jj * 2 + j;
                    float p0 = ex2(sacc[mi][j][0]);
                    float p1 = ex2(sacc[mi][j][1]);
                    float p2 = ex2(sacc[mi][j][2]);
                    float p3 = ex2(sacc[mi][j][3]);
                    if (need_mask) {
                        int jg = jt * BJ + nt * 8 + ((lane & 3) << 1);
                        if (jg     > ig0)     p0 = 0.0f;
                        if (jg + 1 > ig0)     p1 = 0.0f;
                        if (jg     > ig0 + 8) p2 = 0.0f;
                        if (jg + 1 > ig0 + 8) p3 = 0.0f;
                    }
                    dsum[mi][0] += p0 + p1;
                    dsum[mi][1] += p2 + p3;
                    __half2 h01 = __floats2half2_rn(p0, p1);
                    __half2 h23 = __floats2half2_rn(p2, p3);
                    pa[mi][j][0] = *(uint32_t*)&h01;
                    pa[mi][j][1] = *(uint32_t*)&h23;
                }
            }

            uint32_t vf[4][4];
#pragma unroll
            for (int dd = 0; dd < 4; dd++)
                ldm_x4t(vf[dd],
                        smem_u32(&vbuf[(jj * 16 + (lane & 15)) * LDH +
                                       dd * 16 + ((lane >> 4) << 3)]));
#pragma unroll
            for (int mi = 0; mi < 2; mi++) {
                uint32_t af[4] = { pa[mi][0][0], pa[mi][0][1],
                                   pa[mi][1][0], pa[mi][1][1] };
#pragma unroll
                for (int dd = 0; dd < 4; dd++) {
                    mma16816(yacc[mi][dd * 2],     af, vf[dd][0], vf[dd][1]);
                    mma16816(yacc[mi][dd * 2 + 1], af, vf[dd][2], vf[dd][3]);
                }
            }
        }
    };

    int jt = 0;
    for (; jt < 2 * it; jt++) body(jt, false);
    for (; jt <= jt_max; jt++) body(jt, true);

    float inv[2][2];
#pragma unroll
    for (int mi = 0; mi < 2; mi++) {
#pragma unroll
        for (int e = 0; e < 2; e++) {
            float s = dsum[mi][e];
            s += __shfl_xor_sync(0xFFFFFFFFu, s, 1);
            s += __shfl_xor_sync(0xFFFFFFFFu, s, 2);
            inv[mi][e] = 1.0f / s;
        }
    }

    {
        int r = lane >> 2, cb = (lane & 3) << 1;
#pragma unroll
        for (int mi = 0; mi < 2; mi++)
#pragma unroll
            for (int nt = 0; nt < 8; nt++) {
                __half2 h0 = __floats2half2_rn(yacc[mi][nt][0] * inv[mi][0],
                                               yacc[mi][nt][1] * inv[mi][0]);
                __half2 h1 = __floats2half2_rn(yacc[mi][nt][2] * inv[mi][1],
                                               yacc[mi][nt][3] * inv[mi][1]);
                *(__half2*)&Ks[(ilocal + mi * 16 + r) * LDH + nt * 8 + cb] = h0;
                *(__half2*)&Ks[(ilocal + mi * 16 + r + 8) * LDH + nt * 8 + cb] = h1;
            }
    }
    __syncthreads();
    {
        __half* yg = y + (size_t)b * NT * NC + (size_t)h * ND;
#pragma unroll
        for (int i = 0; i < 8; i++) {
            int idx = i * 128 + tid;
            int r = idx >> 3, c = idx & 7;
            *(uint4*)&yg[(size_t)(i0 + r) * NC + c * 8] =
                *(uint4*)&Ks[r * LDH + c * 8];
        }
    }
}

// ---------------------------------------------------------------------------
extern "C" void kernel_launch(void* const* d_in, const int* in_sizes, int n_in,
                              void* d_out, int out_size)
{
    const float* x  = (const float*)d_in[0];
    const float* Wk = (const float*)d_in[1];
    const float* Wq = (const float*)d_in[2];
    const float* Wv = (const float*)d_in[3];
    const float* Wp = (const float*)d_in[4];
    const float* bp = (const float*)d_in[5];
    float* out = (float*)d_out;

    __half *qb, *kb, *vb, *yb, *xh, *wk, *wq, *wv, *wp;
    cudaGetSymbolAddress((void**)&qb, g_q);
    cudaGetSymbolAddress((void**)&kb, g_k);
    cudaGetSymbolAddress((void**)&vb, g_v);
    cudaGetSymbolAddress((void**)&yb, g_y);
    cudaGetSymbolAddress((void**)&xh, g_xh);
    cudaGetSymbolAddress((void**)&wk, g_wk);
    cudaGetSymbolAddress((void**)&wq, g_wq);
    cudaGetSymbolAddress((void**)&wv, g_wv);
    cudaGetSymbolAddress((void**)&wp, g_wp);

    int nsm = 148;
    cudaDeviceGetAttribute(&nsm, cudaDevAttrMultiProcessorCount, 0);
    const int pgrid = 2 * nsm;

    f2h_all_kernel<<<ALLCHUNKS / 256, 256>>>(
        x, Wk, Wq, Wv, Wp, xh, wk, wq, wv, wp);

    cudaFuncSetAttribute(hgemm_kernel,
                         cudaFuncAttributeMaxDynamicSharedMemorySize, GEMM_SMEM);
    hgemm_kernel<<<pgrid, 128, GEMM_SMEM>>>(
        xh, wk, wq, wv, kb, qb, vb, 1536, KSCALE);

    cudaFuncSetAttribute(attn_kernel,
                         cudaFuncAttributeMaxDynamicSharedMemorySize, ATT_SMEM);
    attn_kernel<<<dim3(NB * NH, NT / BI), 128, ATT_SMEM>>>(qb, kb, vb, yb);

    cudaFuncSetAttribute(hgemm_n64_kernel,
                         cudaFuncAttributeMaxDynamicSharedMemorySize, GEMM64_SMEM);
    hgemm_n64_kernel<<<pgrid, 128, GEMM64_SMEM>>>(yb, wp, out, bp, 1024);
}